// round 6
// baseline (speedup 1.0000x reference)
#include <cuda_runtime.h>
#include <math.h>

#define MAX_EDGES 100000
#define MAX_PART  256
#define GRID_BLOCKS (148 * 6)   // one full wave @ 6 blocks/SM

__device__ float g_scores[MAX_EDGES];
__device__ float g_pmax[MAX_PART];
__device__ int   g_pidx[MAX_PART];
__device__ float g_psum[MAX_PART];
__device__ unsigned int g_arrive;   // score-phase arrival counter
__device__ unsigned int g_ticket;   // phase-2 completion ticket

// ---------------------------------------------------------------------------
// ONE persistent kernel:
//   phase 1 (all 888 blocks): s[e] = dot(emb[e], W), grid-stride, 2 edges/warp
//   grid barrier (arrive-and-exit for blocks >= nb2; spin for blocks < nb2)
//   phase 2 (blocks 0..nb2-1): masked logits + flash-softmax partials
//   last ticket block: combine partials, p/logprob/z[p], reset counters
// out: [0]=p, [1]=logprob, [2..257]=z[p]
// ---------------------------------------------------------------------------
__global__ void __launch_bounds__(256) fused_all_kernel(
        const float* __restrict__ emb,
        const float* __restrict__ W,
        const int*   __restrict__ paths,
        const int*   __restrict__ path_lens,
        const int*   __restrict__ path_mask,
        const float* __restrict__ b,
        int n_edges, int n_tiles, int total_warps,
        int n_paths, int max_len, int nb2,
        float* __restrict__ out) {
    __shared__ float smax[256];
    __shared__ int   sidx[256];
    __shared__ float ssum[256];
    __shared__ int   s_is_last;

    int t    = threadIdx.x;
    int lane = t & 31;
    int gw   = (blockIdx.x << 3) + (t >> 5);   // 8 warps/block
    bool path_block = (blockIdx.x < nb2);
    int i = blockIdx.x * 256 + t;              // path index for phase 2

    // ---- preload phase-2 inputs early (independent of scores) ----
    int4 r0, r1, r2, r3;
    int  my_len = 0, my_mask = 0;
    float bias = 0.0f;
    bool live = path_block && (i < n_paths);
    if (live) {
        const int4* row = reinterpret_cast<const int4*>(paths + (size_t)i * max_len);
        r0 = row[0]; r1 = row[1]; r2 = row[2]; r3 = row[3];
        my_len  = path_lens[i] + 1;
        my_mask = path_mask[i];
        bias    = b[0];
    }

    // ================= phase 1: edge scores =================
    const float4* w = reinterpret_cast<const float4*>(W);
    float4 w0 = __ldg(&w[lane * 2]);
    float4 w1 = __ldg(&w[lane * 2 + 1]);
    const float4* base = reinterpret_cast<const float4*>(emb);

    for (int tile = gw; tile < n_tiles; tile += total_warps) {
        const float4* p = base + (size_t)tile * 128;
        float4 a0 = __ldcs(&p[lane * 2]);
        float4 a1 = __ldcs(&p[lane * 2 + 1]);
        float4 b0 = __ldcs(&p[64 + lane * 2]);
        float4 b1 = __ldcs(&p[64 + lane * 2 + 1]);

        float accA = a0.x*w0.x + a0.y*w0.y + a0.z*w0.z + a0.w*w0.w
                   + a1.x*w1.x + a1.y*w1.y + a1.z*w1.z + a1.w*w1.w;
        float accB = b0.x*w0.x + b0.y*w0.y + b0.z*w0.z + b0.w*w0.w
                   + b1.x*w1.x + b1.y*w1.y + b1.z*w1.z + b1.w*w1.w;

        #pragma unroll
        for (int o = 16; o; o >>= 1) {
            accA += __shfl_xor_sync(0xFFFFFFFFu, accA, o);
            accB += __shfl_xor_sync(0xFFFFFFFFu, accB, o);
        }

        if (lane == 0) {
            int e0 = tile * 2;
            g_scores[e0] = accA;
            if (e0 + 1 < n_edges) g_scores[e0 + 1] = accB;
        }
    }

    // ================= grid barrier =================
    __syncthreads();                 // all warps of block done with phase 1
    if (t == 0) {
        __threadfence();             // release this block's score writes
        atomicAdd(&g_arrive, 1u);
    }
    if (!path_block) return;         // non-path blocks just arrive and exit

    if (t == 0) {
        // spin until all blocks have arrived
        while (atomicAdd(&g_arrive, 0u) < (unsigned)GRID_BLOCKS)
            __nanosleep(128);
    }
    __syncthreads();
    __threadfence();                 // acquire all score writes

    // ================= phase 2: logits + partials =================
    float logit = -INFINITY;
    int   idx   = 0x7FFFFFFF;
    if (live) {
        int e[16] = { r0.x, r0.y, r0.z, r0.w, r1.x, r1.y, r1.z, r1.w,
                      r2.x, r2.y, r2.z, r2.w, r3.x, r3.y, r3.z, r3.w };
        float sum = 0.0f;
        #pragma unroll
        for (int j = 0; j < 16; ++j)
            if (j < my_len) sum += g_scores[e[j]];
        logit = sum / (float)my_len + bias;
        if (my_mask == 0) logit = -1e9f;
        idx = i;
    }

    // block argmax (first-occurrence tiebreak)
    smax[t] = logit; sidx[t] = idx;
    __syncthreads();
    #pragma unroll
    for (int o = 128; o; o >>= 1) {
        if (t < o) {
            float v = smax[t + o]; int j = sidx[t + o];
            if (v > smax[t] || (v == smax[t] && j < sidx[t])) {
                smax[t] = v; sidx[t] = j;
            }
        }
        __syncthreads();
    }
    float bm = smax[0];

    float es = live ? expf(logit - bm) : 0.0f;
    ssum[t] = es;
    __syncthreads();
    #pragma unroll
    for (int o = 128; o; o >>= 1) {
        if (t < o) ssum[t] += ssum[t + o];
        __syncthreads();
    }

    if (t == 0) {
        g_pmax[blockIdx.x] = bm;
        g_pidx[blockIdx.x] = sidx[0];
        g_psum[blockIdx.x] = ssum[0];
        __threadfence();
        unsigned rank = atomicAdd(&g_ticket, 1u);
        s_is_last = (rank == (unsigned)(nb2 - 1));
    }
    __syncthreads();
    if (!s_is_last) return;

    // ================= finalize (last ticket block) =================
    __threadfence();

    float m = (t < nb2) ? g_pmax[t] : -INFINITY;
    int   j = (t < nb2) ? g_pidx[t] : 0x7FFFFFFF;
    smax[t] = m; sidx[t] = j;
    __syncthreads();
    #pragma unroll
    for (int o = 128; o; o >>= 1) {
        if (t < o) {
            float v = smax[t + o]; int k = sidx[t + o];
            if (v > smax[t] || (v == smax[t] && k < sidx[t])) {
                smax[t] = v; sidx[t] = k;
            }
        }
        __syncthreads();
    }
    float M = smax[0];
    int   p = sidx[0];
    __syncthreads();

    float e2 = (t < nb2) ? g_psum[t] * expf(g_pmax[t] - M) : 0.0f;
    ssum[t] = e2;
    __syncthreads();
    #pragma unroll
    for (int o = 128; o; o >>= 1) {
        if (t < o) ssum[t] += ssum[t + o];
        __syncthreads();
    }

    if (t == 0) {
        out[0] = (float)p;
        out[1] = -logf(ssum[0]);   // logits[p] == M
        g_ticket = 0;              // reset for next graph replay
        g_arrive = 0;
    }

    // z[p]: per-column ragged mean (256 columns, one per thread)
    {
        int len = path_lens[p] + 1;
        const int* row = paths + (size_t)p * max_len;
        float acc = 0.0f;
        for (int k = 0; k < len; ++k)
            acc += emb[(size_t)row[k] * 256 + t];
        out[2 + t] = acc / (float)len;
    }
}

// ---------------------------------------------------------------------------
// Launch
// Inputs: edge_emb f32[100000,256], paths i32[20000,16], path_lens i32[20000],
//         path_mask i32[20000], W f32[1,256], b f32[1], deterministic i32[1]
// ---------------------------------------------------------------------------
extern "C" void kernel_launch(void* const* d_in, const int* in_sizes, int n_in,
                              void* d_out, int out_size) {
    const float* edge_emb  = (const float*)d_in[0];
    const int*   paths     = (const int*)d_in[1];
    const int*   path_lens = (const int*)d_in[2];
    const int*   path_mask = (const int*)d_in[3];
    const float* W         = (const float*)d_in[4];
    const float* b         = (const float*)d_in[5];

    int hidden  = in_sizes[4];              // 256
    int n_edges = in_sizes[0] / hidden;     // 100000
    int n_paths = in_sizes[2];              // 20000
    int max_len = in_sizes[1] / n_paths;    // 16

    float* out = (float*)d_out;

    int n_tiles = (n_edges + 1) / 2;        // 50000 (2 edges per tile)
    int total_warps = GRID_BLOCKS * 8;      // 7104
    int nb2 = (n_paths + 255) / 256;        // 79

    fused_all_kernel<<<GRID_BLOCKS, 256>>>(edge_emb, W,
                                           paths, path_lens, path_mask, b,
                                           n_edges, n_tiles, total_warps,
                                           n_paths, max_len, nb2, out);
}

// round 7
// speedup vs baseline: 1.2465x; 1.2465x over previous
#include <cuda_runtime.h>
#include <math.h>

#define MAX_EDGES 100000
#define MAX_PART  256

__device__ float g_scores[MAX_EDGES];
__device__ float g_pmax[MAX_PART];
__device__ int   g_pidx[MAX_PART];
__device__ float g_psum[MAX_PART];
__device__ unsigned int g_ticket;   // zero-init; last block resets each run

// ---------------------------------------------------------------------------
// Kernel 1: s[e] = dot(edge_emb[e,:256], W)   [R2 known-best: 18.5us, 32 regs]
// One warp per TWO edges; 4 independent LDG.128 per lane.
// Triggers programmatic completion after its stores so the PDL secondary
// can be fully resident before the grid drains.
// ---------------------------------------------------------------------------
__global__ void __launch_bounds__(256) score_kernel(
        const float* __restrict__ emb,
        const float* __restrict__ W,
        float* __restrict__ s,
        int n_edges) {
    int warp = (blockIdx.x * blockDim.x + threadIdx.x) >> 5;
    int lane = threadIdx.x & 31;
    int e0 = warp * 2;

    if (e0 < n_edges) {
        const float4* w = reinterpret_cast<const float4*>(W);
        float4 w0 = __ldg(&w[lane * 2]);
        float4 w1 = __ldg(&w[lane * 2 + 1]);

        const float4* p0 = reinterpret_cast<const float4*>(emb + (size_t)e0 * 256);
        const float4* p1 = p0 + 64;

        float4 a0 = p0[lane * 2];
        float4 a1 = p0[lane * 2 + 1];
        float4 b0 = p1[lane * 2];
        float4 b1 = p1[lane * 2 + 1];

        float accA = a0.x*w0.x + a0.y*w0.y + a0.z*w0.z + a0.w*w0.w
                   + a1.x*w1.x + a1.y*w1.y + a1.z*w1.z + a1.w*w1.w;
        float accB = b0.x*w0.x + b0.y*w0.y + b0.z*w0.z + b0.w*w0.w
                   + b1.x*w1.x + b1.y*w1.y + b1.z*w1.z + b1.w*w1.w;

        #pragma unroll
        for (int o = 16; o; o >>= 1) {
            accA += __shfl_xor_sync(0xFFFFFFFFu, accA, o);
            accB += __shfl_xor_sync(0xFFFFFFFFu, accB, o);
        }

        if (lane == 0) {
            s[e0] = accA;
            if (e0 + 1 < n_edges) s[e0 + 1] = accB;
        }
    }

    cudaTriggerProgrammaticLaunchCompletion();
}

// ---------------------------------------------------------------------------
// Kernel 2 (fused, PDL secondary): launches while score_kernel runs.
// Preamble (path rows / lens / mask / bias) overlaps the score phase;
// cudaGridDependencySynchronize() gates only the score gathers.
// Per-block flash-softmax partials; last ticket block finalizes:
//   p = argmax (first-occurrence), logprob = -log(sum exp(l - M)), z[p].
// out: [0]=p, [1]=logprob, [2..257]=z[p]
// ---------------------------------------------------------------------------
__global__ void __launch_bounds__(256) paths_fused_kernel(
        const int* __restrict__ paths,
        const int* __restrict__ path_lens,
        const int* __restrict__ path_mask,
        const float* __restrict__ s,
        const float* __restrict__ b,
        const float* __restrict__ emb,
        int n_paths, int max_len, int n_blocks,
        float* __restrict__ out) {
    __shared__ float smax[256];
    __shared__ int   sidx[256];
    __shared__ float ssum[256];
    __shared__ int   s_is_last;

    int t = threadIdx.x;
    int i = blockIdx.x * 256 + t;
    bool live = (i < n_paths);

    // ---- preamble: score-independent loads (overlap the primary) ----
    int4 r0 = make_int4(0,0,0,0), r1 = r0, r2 = r0, r3 = r0;
    int  my_len = 1, my_mask = 0;
    float bias = 0.0f;
    if (live) {
        const int4* row = reinterpret_cast<const int4*>(paths + (size_t)i * max_len);
        r0 = row[0]; r1 = row[1]; r2 = row[2]; r3 = row[3];
        my_len  = path_lens[i] + 1;
        my_mask = path_mask[i];
        bias    = b[0];
    }

    // ---- wait for score_kernel's writes to be visible ----
    cudaGridDependencySynchronize();

    // ---- per-thread logit ----
    float logit = -INFINITY;
    int   idx   = 0x7FFFFFFF;
    if (live) {
        int e[16] = { r0.x, r0.y, r0.z, r0.w, r1.x, r1.y, r1.z, r1.w,
                      r2.x, r2.y, r2.z, r2.w, r3.x, r3.y, r3.z, r3.w };
        float sum = 0.0f;
        #pragma unroll
        for (int j = 0; j < 16; ++j)
            if (j < my_len) sum += s[e[j]];
        logit = sum / (float)my_len + bias;
        if (my_mask == 0) logit = -1e9f;
        idx = i;
    }

    // ---- block argmax (first-occurrence tiebreak) ----
    smax[t] = logit; sidx[t] = idx;
    __syncthreads();
    #pragma unroll
    for (int o = 128; o; o >>= 1) {
        if (t < o) {
            float v = smax[t + o]; int j = sidx[t + o];
            if (v > smax[t] || (v == smax[t] && j < sidx[t])) {
                smax[t] = v; sidx[t] = j;
            }
        }
        __syncthreads();
    }
    float bm = smax[0];

    // ---- block sumexp vs block max ----
    float es = live ? expf(logit - bm) : 0.0f;
    ssum[t] = es;
    __syncthreads();
    #pragma unroll
    for (int o = 128; o; o >>= 1) {
        if (t < o) ssum[t] += ssum[t + o];
        __syncthreads();
    }

    // ---- publish partials, draw ticket ----
    if (t == 0) {
        g_pmax[blockIdx.x] = bm;
        g_pidx[blockIdx.x] = sidx[0];
        g_psum[blockIdx.x] = ssum[0];
        __threadfence();
        unsigned rank = atomicAdd(&g_ticket, 1u);
        s_is_last = (rank == (unsigned)(n_blocks - 1));
    }
    __syncthreads();
    if (!s_is_last) return;

    // ===== last block: finalize =====
    __threadfence();

    float m = (t < n_blocks) ? g_pmax[t] : -INFINITY;
    int   j = (t < n_blocks) ? g_pidx[t] : 0x7FFFFFFF;
    smax[t] = m; sidx[t] = j;
    __syncthreads();
    #pragma unroll
    for (int o = 128; o; o >>= 1) {
        if (t < o) {
            float v = smax[t + o]; int k = sidx[t + o];
            if (v > smax[t] || (v == smax[t] && k < sidx[t])) {
                smax[t] = v; sidx[t] = k;
            }
        }
        __syncthreads();
    }
    float M = smax[0];
    int   p = sidx[0];
    __syncthreads();

    float e2 = (t < n_blocks) ? g_psum[t] * expf(g_pmax[t] - M) : 0.0f;
    ssum[t] = e2;
    __syncthreads();
    #pragma unroll
    for (int o = 128; o; o >>= 1) {
        if (t < o) ssum[t] += ssum[t + o];
        __syncthreads();
    }

    if (t == 0) {
        out[0] = (float)p;
        out[1] = -logf(ssum[0]);   // logits[p] == M
        g_ticket = 0;              // reset for next graph replay
    }

    // z[p]: per-column ragged mean (256 columns, one per thread)
    {
        int len = path_lens[p] + 1;
        const int* row = paths + (size_t)p * max_len;
        float acc = 0.0f;
        for (int k = 0; k < len; ++k)
            acc += emb[(size_t)row[k] * 256 + t];
        out[2 + t] = acc / (float)len;
    }
}

// ---------------------------------------------------------------------------
// Launch
// Inputs: edge_emb f32[100000,256], paths i32[20000,16], path_lens i32[20000],
//         path_mask i32[20000], W f32[1,256], b f32[1], deterministic i32[1]
// ---------------------------------------------------------------------------
extern "C" void kernel_launch(void* const* d_in, const int* in_sizes, int n_in,
                              void* d_out, int out_size) {
    const float* edge_emb  = (const float*)d_in[0];
    const int*   paths     = (const int*)d_in[1];
    const int*   path_lens = (const int*)d_in[2];
    const int*   path_mask = (const int*)d_in[3];
    const float* W         = (const float*)d_in[4];
    const float* b         = (const float*)d_in[5];

    int hidden  = in_sizes[4];              // 256
    int n_edges = in_sizes[0] / hidden;     // 100000
    int n_paths = in_sizes[2];              // 20000
    int max_len = in_sizes[1] / n_paths;    // 16

    float* out = (float*)d_out;

    float* scores; cudaGetSymbolAddress((void**)&scores, g_scores);

    // K1: 2 edges per warp, 8 warps per block (known-best config)
    {
        int edges_per_block = 16;
        int blocks = (n_edges + edges_per_block - 1) / edges_per_block;
        score_kernel<<<blocks, 256>>>(edge_emb, W, scores, n_edges);
    }

    // K2 fused, launched as PDL secondary so it overlaps K1.
    int nb2 = (n_paths + 255) / 256;        // 79

    cudaLaunchConfig_t cfg = {};
    cfg.gridDim  = dim3((unsigned)nb2, 1, 1);
    cfg.blockDim = dim3(256, 1, 1);
    cfg.dynamicSmemBytes = 0;
    cfg.stream = 0;
    cudaLaunchAttribute attrs[1];
    attrs[0].id = cudaLaunchAttributeProgrammaticStreamSerialization;
    attrs[0].val.programmaticStreamSerializationAllowed = 1;
    cfg.attrs = attrs;
    cfg.numAttrs = 1;

    cudaLaunchKernelEx(&cfg, paths_fused_kernel,
                       paths, path_lens, path_mask,
                       (const float*)scores, b, edge_emb,
                       n_paths, max_len, nb2, out);
}